// round 5
// baseline (speedup 1.0000x reference)
#include <cuda_runtime.h>
#include <limits.h>

// Problem constants (fixed by setup_inputs)
#define N_PERK 16384
#define NQK    4096      // B * M_PER
#define CINF   16
#define NS0    16
#define NS1    32
#define NT0    65536     // NQK * NS0
#define NT1    131072    // NQK * NS1

// channel offsets into the 144-wide BN stat arrays
#define OFF_S0L1 0
#define OFF_S0L2 16
#define OFF_S1L1 48
#define OFF_S1L2 80

#define GRIDR  10
#define NCELLS 1000
#define CAP1   768
#define CAP0   192

#define NB     592       // 4 blocks x 148 SMs: all co-resident by construction
#define NTHR   128

// ---------------- scratch (device globals; no allocation allowed) ----------
struct Scratch {
    int      cellcnt[2016];
    int      cellofs[2016];
    double   sum[144];
    double   sqs[144];
    unsigned bar[8];
};
__device__ Scratch d_scr;
__device__ int    d_cellstart[2048];
__device__ float4 d_pts4 [2 * N_PERK]; // original order: (x,y,z,|p|^2)
__device__ float4 d_cpts4[2 * N_PERK]; // cell-sorted:    (x,y,z,idx_bits)
__device__ float  d_g0 [19 * NT0];
__device__ float  d_g1 [19 * NT1];
__device__ float  d_xa0[16 * NT0];
__device__ float  d_xb0[32 * NT0];
__device__ float  d_xa1[32 * NT1];
__device__ float  d_xb1[64 * NT1];

// ---------------- shared memory phase overlays -----------------------------
struct BQSh {
    int cand1[4][CAP1];
    int cand0[4][CAP0];
    int bc1[4][32], bc0[4][32];
    int sel2[4][64];
    int fin1[4][NS1], fin0[4][NS0];
};                                        // 18176 B
struct ScanSh { int a[2048], b[2048]; };  // 16384 B
struct GemvSh {
    float w[64 * 32];
    float sS[32], sB[32];
    float shm[64], shq[64];
};                                        // 8960 B
struct PoolSh { float psc[64], pbi[64]; };

// ---------------- software grid barrier ------------------------------------
// Counters live in d_scr.bar, zeroed by the memset node before every launch.
__device__ __forceinline__ void gridbar(int i)
{
    __syncthreads();
    if (threadIdx.x == 0) {
        __threadfence();
        atomicAdd(&d_scr.bar[i], 1u);
        while (*(volatile unsigned*)&d_scr.bar[i] < (unsigned)NB)
            __nanosleep(64);
    }
    __syncthreads();
}

// ---------------- phase 0: pack points + count cells ------------------------
__device__ void prep_phase(const float* __restrict__ xyz)
{
    int i = blockIdx.x * NTHR + threadIdx.x;
    if (i < 2 * N_PERK) {
        float x = xyz[i*3+0], y = xyz[i*3+1], z = xyz[i*3+2];
        d_pts4[i] = make_float4(x, y, z, fmaf(z, z, fmaf(y, y, x*x)));
        int cx = min(GRIDR-1, max(0, (int)(x * 10.f)));
        int cy = min(GRIDR-1, max(0, (int)(y * 10.f)));
        int cz = min(GRIDR-1, max(0, (int)(z * 10.f)));
        int cell = (i >> 14) * NCELLS + (cz * GRIDR + cy) * GRIDR + cx;
        atomicAdd(&d_scr.cellcnt[cell], 1);
    }
}

// ---------------- phase 1: exclusive scan (block 0 only) -------------------
__device__ void scan_phase(ScanSh& S)
{
    int t = threadIdx.x;
    for (int k = t; k < 2048; k += NTHR)
        S.a[k] = (k < 2 * NCELLS) ? d_scr.cellcnt[k] : 0;
    __syncthreads();
    int *src = S.a, *dst = S.b;
    for (int off = 1; off < 2048; off <<= 1) {
        for (int k = t; k < 2048; k += NTHR) {
            int v = src[k];
            if (k >= off) v += src[k - off];
            dst[k] = v;
        }
        __syncthreads();
        int* tmp = src; src = dst; dst = tmp;
    }
    for (int k = t; k < 2 * NCELLS; k += NTHR)
        d_cellstart[k] = (k == 0) ? 0 : src[k - 1];
    if (t == 0) d_cellstart[2 * NCELLS] = src[2 * NCELLS - 1];
    __syncthreads();
}

// ---------------- phase 2: scatter into cell-sorted array ------------------
__device__ void scatter_phase()
{
    int i = blockIdx.x * NTHR + threadIdx.x;
    if (i < 2 * N_PERK) {
        float4 p = d_pts4[i];
        int cx = min(GRIDR-1, max(0, (int)(p.x * 10.f)));
        int cy = min(GRIDR-1, max(0, (int)(p.y * 10.f)));
        int cz = min(GRIDR-1, max(0, (int)(p.z * 10.f)));
        int cell = (i >> 14) * NCELLS + (cz * GRIDR + cy) * GRIDR + cx;
        int pos = d_cellstart[cell] + atomicAdd(&d_scr.cellofs[cell], 1);
        d_cpts4[pos] = make_float4(p.x, p.y, p.z, __int_as_float(i & (N_PERK-1)));
    }
}

// ---------------- select k smallest indices from cand[cnt] -----------------
__device__ __forceinline__ int select_k(const int* __restrict__ cand, int cnt,
                                        const int* __restrict__ bc,
                                        int* __restrict__ sel2,
                                        int* __restrict__ fin,
                                        int k, int lane, unsigned low)
{
    if (cnt <= k) {
        for (int i = lane; i < cnt; i += 32) fin[i] = cand[i];
        return cnt;
    }
    int p = bc[lane];
    #pragma unroll
    for (int d = 1; d < 32; d <<= 1) {
        int t = __shfl_up_sync(0xffffffffu, p, d);
        if (lane >= d) p += t;
    }
    unsigned mk = __ballot_sync(0xffffffffu, p >= k);
    int bstar = __ffs(mk) - 1;
    int base  = (bstar > 0) ? __shfl_sync(0xffffffffu, p, bstar - 1) : 0;
    int need  = k - base;
    int B0 = bstar << 9, B1 = (bstar + 1) << 9;

    int n_auto = 0, n_mid = 0;
    for (int i0 = 0; i0 < cnt; i0 += 32) {
        int i = i0 + lane;
        int v = (i < cnt) ? cand[i] : INT_MAX;
        bool a = (v < B0);
        bool m = (v >= B0) && (v < B1);
        unsigned ma = __ballot_sync(0xffffffffu, a);
        unsigned mm = __ballot_sync(0xffffffffu, m);
        if (a) fin[n_auto + __popc(ma & low)] = v;
        else if (m) {
            int pos = n_mid + __popc(mm & low);
            if (pos < 64) sel2[pos] = v;
        }
        n_auto += __popc(ma);
        n_mid  += __popc(mm);
    }
    if (n_mid > 64) n_mid = 64;
    __syncwarp();

    int last = -1;
    for (int j = 0; j < need; j++) {
        int v = INT_MAX;
        for (int i = lane; i < n_mid; i += 32) {
            int x = sel2[i];
            if (x > last && x < v) v = x;
        }
        #pragma unroll
        for (int d = 16; d; d >>= 1)
            v = min(v, __shfl_xor_sync(0xffffffffu, v, d));
        fin[base + j] = v;
        last = v;
    }
    return k;
}

// ---------------- phase 3: fused dual-scale ball query + grouping ----------
__device__ void bq_phase(BQSh& S, const float* __restrict__ nxyz,
                         const float* __restrict__ feat)
{
    int w    = threadIdx.x >> 5;
    int lane = threadIdx.x & 31;
    unsigned low = (1u << lane) - 1u;
    const float RP2 = 0.04f + 1e-4f;

    for (int q = blockIdx.x * 4 + w; q < NQK; q += NB * 4) {
        int b = q >> 11;
        int nbase = b << 14;

        S.bc1[w][lane] = 0;
        S.bc0[w][lane] = 0;

        float qx = nxyz[q*3+0], qy = nxyz[q*3+1], qz = nxyz[q*3+2];
        float q2 = fmaf(qz, qz, fmaf(qy, qy, qx*qx));

        int cy = min(GRIDR-1, max(0, (int)(qy * 10.f)));
        int cz = min(GRIDR-1, max(0, (int)(qz * 10.f)));

        int cnt1 = 0, cnt0 = 0;
        int lmin1 = INT_MAX, lmin0 = INT_MAX;
        __syncwarp();

        int zlo = max(0, cz-2), zhi = min(GRIDR-1, cz+2);
        int ylo = max(0, cy-2), yhi = min(GRIDR-1, cy+2);
        for (int zz = zlo; zz <= zhi; zz++) {
            float dz = fmaxf(0.f, fmaxf(zz * 0.1f - qz, qz - (zz+1) * 0.1f));
            float dz2 = dz * dz;
            if (dz2 >= RP2) continue;
            for (int yy = ylo; yy <= yhi; yy++) {
                float dy = fmaxf(0.f, fmaxf(yy * 0.1f - qy, qy - (yy+1) * 0.1f));
                float r2 = fmaf(dy, dy, dz2);
                if (r2 >= RP2) continue;
                float dxm = sqrtf(RP2 - r2);
                int xlo = max(0, (int)floorf((qx - dxm) * 10.f));
                int xhi = min(GRIDR-1, (int)floorf((qx + dxm) * 10.f));
                if (xlo > xhi) continue;
                int row = b * NCELLS + (zz * GRIDR + yy) * GRIDR;
                int s = d_cellstart[row + xlo];
                int e = d_cellstart[row + xhi + 1];
                for (int i0 = s; i0 < e; i0 += 32) {
                    int i = i0 + lane;
                    bool ok1 = false, ok0 = false;
                    int idx = 0;
                    if (i < e) {
                        float4 p = d_cpts4[i];
                        idx = __float_as_int(p.w);
                        float p2 = fmaf(p.z, p.z, fmaf(p.y, p.y, p.x*p.x));
                        float dt = fmaf(qz, p.z, fmaf(qy, p.y, qx*p.x));
                        float d2 = fmaf(-2.f, dt, q2 + p2);
                        ok1 = d2 < 0.04f;
                        ok0 = d2 < 0.01f;
                    }
                    unsigned m1 = __ballot_sync(0xffffffffu, ok1);
                    unsigned m0 = __ballot_sync(0xffffffffu, ok0);
                    if (ok1) {
                        lmin1 = min(lmin1, idx);
                        int pos = cnt1 + __popc(m1 & low);
                        if (pos < CAP1) {
                            S.cand1[w][pos] = idx;
                            atomicAdd(&S.bc1[w][idx >> 9], 1);
                        }
                    }
                    if (ok0) {
                        lmin0 = min(lmin0, idx);
                        int pos = cnt0 + __popc(m0 & low);
                        if (pos < CAP0) {
                            S.cand0[w][pos] = idx;
                            atomicAdd(&S.bc0[w][idx >> 9], 1);
                        }
                    }
                    cnt1 += __popc(m1);
                    cnt0 += __popc(m0);
                }
            }
        }
        cnt1 = min(cnt1, CAP1);
        cnt0 = min(cnt0, CAP0);
        #pragma unroll
        for (int d = 16; d; d >>= 1) {
            lmin1 = min(lmin1, __shfl_xor_sync(0xffffffffu, lmin1, d));
            lmin0 = min(lmin0, __shfl_xor_sync(0xffffffffu, lmin0, d));
        }
        __syncwarp();

        int m1n = select_k(S.cand1[w], cnt1, S.bc1[w], S.sel2[w], S.fin1[w], NS1, lane, low);
        __syncwarp();
        int m0n = select_k(S.cand0[w], cnt0, S.bc0[w], S.sel2[w], S.fin0[w], NS0, lane, low);
        __syncwarp();

        {   // scale 1 grouping
            int sidx = q * NS1 + lane;
            float g[19];
            if (m1n == 0) {
                #pragma unroll
                for (int c = 0; c < 19; c++) g[c] = 0.f;
            } else {
                int id = (lane < m1n) ? S.fin1[w][lane] : lmin1;
                float4 p = d_pts4[nbase + id];
                g[0] = p.x - qx; g[1] = p.y - qy; g[2] = p.z - qz;
                const float4* f = (const float4*)(feat + (size_t)(nbase + id) * CINF);
                float4 f0 = f[0], f1 = f[1], f2 = f[2], f3 = f[3];
                g[3]=f0.x; g[4]=f0.y; g[5]=f0.z; g[6]=f0.w;
                g[7]=f1.x; g[8]=f1.y; g[9]=f1.z; g[10]=f1.w;
                g[11]=f2.x; g[12]=f2.y; g[13]=f2.z; g[14]=f2.w;
                g[15]=f3.x; g[16]=f3.y; g[17]=f3.z; g[18]=f3.w;
            }
            #pragma unroll
            for (int c = 0; c < 19; c++) d_g1[c * NT1 + sidx] = g[c];
        }
        if (lane < NS0) {   // scale 0 grouping
            int sidx = q * NS0 + lane;
            float g[19];
            if (m0n == 0) {
                #pragma unroll
                for (int c = 0; c < 19; c++) g[c] = 0.f;
            } else {
                int id = (lane < m0n) ? S.fin0[w][lane] : lmin0;
                float4 p = d_pts4[nbase + id];
                g[0] = p.x - qx; g[1] = p.y - qy; g[2] = p.z - qz;
                const float4* f = (const float4*)(feat + (size_t)(nbase + id) * CINF);
                float4 f0 = f[0], f1 = f[1], f2 = f[2], f3 = f[3];
                g[3]=f0.x; g[4]=f0.y; g[5]=f0.z; g[6]=f0.w;
                g[7]=f1.x; g[8]=f1.y; g[9]=f1.z; g[10]=f1.w;
                g[11]=f2.x; g[12]=f2.y; g[13]=f2.z; g[14]=f2.w;
                g[15]=f3.x; g[16]=f3.y; g[17]=f3.z; g[18]=f3.w;
            }
            #pragma unroll
            for (int c = 0; c < 19; c++) d_g0[c * NT0 + sidx] = g[c];
        }
    }
}

// ---------------- GEMV phase (one pass; covers ntot with grid threads) -----
template<int CIN, int CINP, int COUT, bool AFF>
__device__ void gemv_phase(GemvSh& G, const float* __restrict__ in, int ntot,
                           const float* __restrict__ W,
                           const float* __restrict__ gamma_,
                           const float* __restrict__ beta_,
                           float pN, int poff,
                           float* __restrict__ out, int off)
{
    for (int i = threadIdx.x; i < COUT * CINP; i += NTHR) {
        int o = i / CINP, c = i % CINP;
        G.w[i] = (c < CIN) ? W[o * CIN + c] : 0.f;
    }
    for (int i = threadIdx.x; i < COUT; i += NTHR) { G.shm[i] = 0.f; G.shq[i] = 0.f; }
    if (AFF) {
        for (int i = threadIdx.x; i < CIN; i += NTHR) {
            double inv  = 1.0 / (double)pN;
            double mean = d_scr.sum[poff + i] * inv;
            double var  = d_scr.sqs[poff + i] * inv - mean * mean;
            double sc   = (double)gamma_[i] * rsqrt(var + 1e-5);
            G.sS[i] = (float)sc;
            G.sB[i] = (float)((double)beta_[i] - mean * sc);
        }
    }
    __syncthreads();

    int s    = (blockIdx.x * NTHR + threadIdx.x) * 2;
    bool act = s < ntot;
    int lane = threadIdx.x & 31;

    float2 x[CINP];
    #pragma unroll
    for (int c = 0; c < CINP; c++) {
        float2 v = make_float2(0.f, 0.f);
        if (c < CIN && act) {
            v = *(const float2*)&in[(size_t)c * ntot + s];
            if (AFF) {
                v.x = fmaxf(fmaf(v.x, G.sS[c], G.sB[c]), 0.f);
                v.y = fmaxf(fmaf(v.y, G.sS[c], G.sB[c]), 0.f);
            }
        }
        x[c] = v;
    }

    const float4* sW4 = (const float4*)G.w;
    #pragma unroll
    for (int o = 0; o < COUT; o++) {
        float ax = 0.f, ay = 0.f;
        #pragma unroll
        for (int c4 = 0; c4 < CINP / 4; c4++) {
            float4 wv = sW4[o * (CINP / 4) + c4];
            ax = fmaf(x[c4*4+0].x, wv.x, ax); ay = fmaf(x[c4*4+0].y, wv.x, ay);
            ax = fmaf(x[c4*4+1].x, wv.y, ax); ay = fmaf(x[c4*4+1].y, wv.y, ay);
            ax = fmaf(x[c4*4+2].x, wv.z, ax); ay = fmaf(x[c4*4+2].y, wv.z, ay);
            ax = fmaf(x[c4*4+3].x, wv.w, ax); ay = fmaf(x[c4*4+3].y, wv.w, ay);
        }
        if (act) *(float2*)&out[(size_t)o * ntot + s] = make_float2(ax, ay);
        float sm = ax + ay;
        float sq = fmaf(ax, ax, ay * ay);
        #pragma unroll
        for (int d = 16; d; d >>= 1) {
            sm += __shfl_down_sync(0xffffffffu, sm, d);
            sq += __shfl_down_sync(0xffffffffu, sq, d);
        }
        if (lane == 0) { atomicAdd(&G.shm[o], sm); atomicAdd(&G.shq[o], sq); }
    }
    __syncthreads();
    if (threadIdx.x < COUT) {
        atomicAdd(&d_scr.sum[off + threadIdx.x], (double)G.shm[threadIdx.x]);
        atomicAdd(&d_scr.sqs[off + threadIdx.x], (double)G.shq[threadIdx.x]);
    }
    __syncthreads();
}

// ---------------- pool phase ------------------------------------------------
template<int NS, int COUT>
__device__ void pool_phase(PoolSh& P, const float* __restrict__ x, int ntot,
                           int off, float pN,
                           const float* __restrict__ gamma_,
                           const float* __restrict__ beta_,
                           int col_off, int out_off, float* __restrict__ out)
{
    if (threadIdx.x < COUT) {
        int i = threadIdx.x;
        double inv  = 1.0 / (double)pN;
        double mean = d_scr.sum[off + i] * inv;
        double var  = d_scr.sqs[off + i] * inv - mean * mean;
        double sc   = (double)gamma_[i] * rsqrt(var + 1e-5);
        P.psc[i] = (float)sc;
        P.pbi[i] = (float)((double)beta_[i] - mean * sc);
    }
    __syncthreads();

    int gwarp = (blockIdx.x * NTHR + threadIdx.x) >> 5;
    int lane  = threadIdx.x & 31;
    const int QPW = 32 / NS;
    const int NWQ = NQK / QPW;
    for (int wq = gwarp; wq < NWQ; wq += NB * 4) {
        int q = wq * QPW + lane / NS;
        int j = lane % NS;
        #pragma unroll 4
        for (int o = 0; o < COUT; o++) {
            float v = fmaf(x[(size_t)o * ntot + q * NS + j], P.psc[o], P.pbi[o]);
            #pragma unroll
            for (int d = NS / 2; d; d >>= 1)
                v = fmaxf(v, __shfl_xor_sync(0xffffffffu, v, d));
            if (j == 0) out[out_off + q * 96 + col_off + o] = fmaxf(v, 0.f);
        }
    }
    __syncthreads();
}

// ---------------- the mega kernel -------------------------------------------
__global__ void __launch_bounds__(NTHR, 4) mega_kernel(
    const float* __restrict__ xyz, const float* __restrict__ nxyz,
    const float* __restrict__ feat,
    const float* w00, const float* g00, const float* b00,
    const float* w01, const float* g01, const float* b01,
    const float* w10, const float* g10, const float* b10,
    const float* w11, const float* g11, const float* b11,
    float* __restrict__ out, int out_off)
{
    __shared__ __align__(16) char smraw[sizeof(BQSh)];

    prep_phase(xyz);
    gridbar(0);
    if (blockIdx.x == 0) scan_phase(*(ScanSh*)smraw);
    gridbar(1);
    scatter_phase();
    gridbar(2);
    bq_phase(*(BQSh*)smraw, nxyz, feat);
    gridbar(3);

    {   // layer 1 (both scales)
        GemvSh& G = *(GemvSh*)smraw;
        gemv_phase<19, 20, 32, false>(G, d_g1, NT1, w10, nullptr, nullptr,
                                      0.f, 0, d_xa1, OFF_S1L1);
        gemv_phase<19, 20, 16, false>(G, d_g0, NT0, w00, nullptr, nullptr,
                                      0.f, 0, d_xa0, OFF_S0L1);
    }
    gridbar(4);
    {   // layer 2 (both scales; BN of layer-1 fused on input)
        GemvSh& G = *(GemvSh*)smraw;
        gemv_phase<32, 32, 64, true>(G, d_xa1, NT1, w11, g10, b10,
                                     (float)NT1, OFF_S1L1, d_xb1, OFF_S1L2);
        gemv_phase<16, 16, 32, true>(G, d_xa0, NT0, w01, g00, b00,
                                     (float)NT0, OFF_S0L1, d_xb0, OFF_S0L2);
    }
    gridbar(5);
    {   // pools (both scales; BN of layer-2 fused)
        PoolSh& P = *(PoolSh*)smraw;
        pool_phase<NS1, 64>(P, d_xb1, NT1, OFF_S1L2, (float)NT1, g11, b11,
                            32, out_off, out);
        __syncthreads();
        pool_phase<NS0, 32>(P, d_xb0, NT0, OFF_S0L2, (float)NT0, g01, b01,
                            0, out_off, out);
    }
}

// ---------------- launch ----------------------------------------------------
extern "C" void kernel_launch(void* const* d_in, const int* in_sizes, int n_in,
                              void* d_out, int out_size)
{
    const float* xyz  = (const float*)d_in[0];
    const float* nxyz = (const float*)d_in[2];
    const float* feat = (const float*)d_in[4];
    const float* w00 = (const float*)d_in[5];
    const float* g00 = (const float*)d_in[6];
    const float* b00 = (const float*)d_in[7];
    const float* w01 = (const float*)d_in[8];
    const float* g01 = (const float*)d_in[9];
    const float* b01 = (const float*)d_in[10];
    const float* w10 = (const float*)d_in[11];
    const float* g10 = (const float*)d_in[12];
    const float* b10 = (const float*)d_in[13];
    const float* w11 = (const float*)d_in[14];
    const float* g11 = (const float*)d_in[15];
    const float* b11 = (const float*)d_in[16];
    float* out = (float*)d_out;

    void* scr;
    cudaGetSymbolAddress(&scr, d_scr);

    int out_off = out_size - NQK * 96;
    if (out_off < 0) out_off = 0;
    if (out_off > 0)
        cudaMemcpyAsync(out, nxyz, (size_t)out_off * sizeof(float),
                        cudaMemcpyDeviceToDevice);

    cudaMemsetAsync(scr, 0, sizeof(Scratch));

    mega_kernel<<<NB, NTHR>>>(xyz, nxyz, feat,
                              w00, g00, b00, w01, g01, b01,
                              w10, g10, b10, w11, g11, b11,
                              out, out_off);
}

// round 6
// speedup vs baseline: 1.7618x; 1.7618x over previous
#include <cuda_runtime.h>
#include <limits.h>

// Problem constants (fixed by setup_inputs)
#define N_PERK 16384
#define NQK    4096      // B * M_PER
#define CINF   16
#define NS0    16
#define NS1    32
#define NT0    65536     // NQK * NS0
#define NT1    131072    // NQK * NS1

// channel offsets into the 144-wide BN stat arrays
#define OFF_S0L1 0
#define OFF_S0L2 16
#define OFF_S1L1 48
#define OFF_S1L2 80

#define GRIDR  10
#define NCELLS 1000
#define CAP1   768
#define CAP0   192

// ---------------- scratch (device globals; no allocation allowed) ----------
struct Scratch {
    int    cellcnt[2016];
    int    cellofs[2016];
    double sum[144];
    double sqs[144];
};
__device__ Scratch d_scr;
__device__ int    d_cellstart[2048];
__device__ float4 d_pts4 [2 * N_PERK]; // original order: (x,y,z,|p|^2)
__device__ float4 d_cpts4[2 * N_PERK]; // cell-sorted:    (x,y,z,idx_bits)
__device__ float  d_g0 [19 * NT0];
__device__ float  d_g1 [19 * NT1];
__device__ float  d_xa0[16 * NT0];
__device__ float  d_xb0[32 * NT0];
__device__ float  d_xa1[32 * NT1];
__device__ float  d_xb1[64 * NT1];

// ---------------- kernel 0: pack points + count cells -----------------------
__global__ void prep_count_kernel(const float* __restrict__ xyz)
{
    int i = blockIdx.x * blockDim.x + threadIdx.x;
    if (i >= 2 * N_PERK) return;
    float x = xyz[i*3+0], y = xyz[i*3+1], z = xyz[i*3+2];
    d_pts4[i] = make_float4(x, y, z, fmaf(z, z, fmaf(y, y, x*x)));
    int cx = min(GRIDR-1, max(0, (int)(x * 10.f)));
    int cy = min(GRIDR-1, max(0, (int)(y * 10.f)));
    int cz = min(GRIDR-1, max(0, (int)(z * 10.f)));
    int cell = (i >> 14) * NCELLS + (cz * GRIDR + cy) * GRIDR + cx;
    atomicAdd(&d_scr.cellcnt[cell], 1);
}

// ---------------- kernel 1: exclusive scan of 2000 cell counts -------------
__global__ void scan_kernel()
{
    __shared__ int a[2048], b[2048];
    int t = threadIdx.x;
    for (int k = t; k < 2048; k += 1024)
        a[k] = (k < 2 * NCELLS) ? d_scr.cellcnt[k] : 0;
    __syncthreads();
    int *src = a, *dst = b;
    for (int off = 1; off < 2048; off <<= 1) {
        for (int k = t; k < 2048; k += 1024) {
            int v = src[k];
            if (k >= off) v += src[k - off];
            dst[k] = v;
        }
        __syncthreads();
        int* tmp = src; src = dst; dst = tmp;
    }
    for (int k = t; k < 2 * NCELLS; k += 1024)
        d_cellstart[k] = (k == 0) ? 0 : src[k - 1];
    if (t == 0) d_cellstart[2 * NCELLS] = src[2 * NCELLS - 1];
}

// ---------------- kernel 2: scatter points into cell-sorted array ----------
__global__ void scatter_kernel()
{
    int i = blockIdx.x * blockDim.x + threadIdx.x;
    if (i >= 2 * N_PERK) return;
    float4 p = d_pts4[i];
    int cx = min(GRIDR-1, max(0, (int)(p.x * 10.f)));
    int cy = min(GRIDR-1, max(0, (int)(p.y * 10.f)));
    int cz = min(GRIDR-1, max(0, (int)(p.z * 10.f)));
    int cell = (i >> 14) * NCELLS + (cz * GRIDR + cy) * GRIDR + cx;
    int pos = d_cellstart[cell] + atomicAdd(&d_scr.cellofs[cell], 1);
    d_cpts4[pos] = make_float4(p.x, p.y, p.z, __int_as_float(i & (N_PERK - 1)));
}

// ---------------- select k smallest indices from cand[cnt] -----------------
__device__ __forceinline__ int select_k(const int* __restrict__ cand, int cnt,
                                        const int* __restrict__ bc,
                                        int* __restrict__ sel2,
                                        int* __restrict__ fin,
                                        int k, int lane, unsigned low)
{
    if (cnt <= k) {
        for (int i = lane; i < cnt; i += 32) fin[i] = cand[i];
        return cnt;
    }
    int p = bc[lane];
    #pragma unroll
    for (int d = 1; d < 32; d <<= 1) {
        int t = __shfl_up_sync(0xffffffffu, p, d);
        if (lane >= d) p += t;
    }
    unsigned mk = __ballot_sync(0xffffffffu, p >= k);
    int bstar = __ffs(mk) - 1;
    int base  = (bstar > 0) ? __shfl_sync(0xffffffffu, p, bstar - 1) : 0;
    int need  = k - base;
    int B0 = bstar << 9, B1 = (bstar + 1) << 9;

    int n_auto = 0, n_mid = 0;
    for (int i0 = 0; i0 < cnt; i0 += 32) {
        int i = i0 + lane;
        int v = (i < cnt) ? cand[i] : INT_MAX;
        bool a = (v < B0);
        bool m = (v >= B0) && (v < B1);
        unsigned ma = __ballot_sync(0xffffffffu, a);
        unsigned mm = __ballot_sync(0xffffffffu, m);
        if (a) fin[n_auto + __popc(ma & low)] = v;
        else if (m) {
            int pos = n_mid + __popc(mm & low);
            if (pos < 64) sel2[pos] = v;
        }
        n_auto += __popc(ma);
        n_mid  += __popc(mm);
    }
    if (n_mid > 64) n_mid = 64;
    __syncwarp();

    int last = -1;
    for (int j = 0; j < need; j++) {
        int v = INT_MAX;
        for (int i = lane; i < n_mid; i += 32) {
            int x = sel2[i];
            if (x > last && x < v) v = x;
        }
        #pragma unroll
        for (int d = 16; d; d >>= 1)
            v = min(v, __shfl_xor_sync(0xffffffffu, v, d));
        fin[base + j] = v;
        last = v;
    }
    return k;
}

// ---------------- kernel 3: fused dual-scale grid ball query + grouping ----
__global__ void __launch_bounds__(128) bq_fused_kernel(
    const float* __restrict__ nxyz, const float* __restrict__ feat)
{
    __shared__ int cand1[4][CAP1];
    __shared__ int cand0[4][CAP0];
    __shared__ int bc1[4][32], bc0[4][32];
    __shared__ int sel2[4][64];
    __shared__ int fin1[4][NS1], fin0[4][NS0];

    int w    = threadIdx.x >> 5;
    int lane = threadIdx.x & 31;
    int q    = blockIdx.x * 4 + w;
    int b    = q >> 11;
    int nbase = b << 14;
    unsigned low = (1u << lane) - 1u;

    bc1[w][lane] = 0;
    bc0[w][lane] = 0;

    float qx = nxyz[q*3+0], qy = nxyz[q*3+1], qz = nxyz[q*3+2];
    float q2 = fmaf(qz, qz, fmaf(qy, qy, qx*qx));

    int cy = min(GRIDR-1, max(0, (int)(qy * 10.f)));
    int cz = min(GRIDR-1, max(0, (int)(qz * 10.f)));

    const float RP2 = 0.04f + 1e-4f;

    int cnt1 = 0, cnt0 = 0;
    int lmin1 = INT_MAX, lmin0 = INT_MAX;
    __syncwarp();

    int zlo = max(0, cz-2), zhi = min(GRIDR-1, cz+2);
    int ylo = max(0, cy-2), yhi = min(GRIDR-1, cy+2);
    for (int zz = zlo; zz <= zhi; zz++) {
        float dz = fmaxf(0.f, fmaxf(zz * 0.1f - qz, qz - (zz+1) * 0.1f));
        float dz2 = dz * dz;
        if (dz2 >= RP2) continue;
        for (int yy = ylo; yy <= yhi; yy++) {
            float dy = fmaxf(0.f, fmaxf(yy * 0.1f - qy, qy - (yy+1) * 0.1f));
            float r2 = fmaf(dy, dy, dz2);
            if (r2 >= RP2) continue;
            float dxm = sqrtf(RP2 - r2);
            int xlo = max(0, (int)floorf((qx - dxm) * 10.f));
            int xhi = min(GRIDR-1, (int)floorf((qx + dxm) * 10.f));
            if (xlo > xhi) continue;
            int row = b * NCELLS + (zz * GRIDR + yy) * GRIDR;
            int s = d_cellstart[row + xlo];
            int e = d_cellstart[row + xhi + 1];
            for (int i0 = s; i0 < e; i0 += 32) {
                int i = i0 + lane;
                bool ok1 = false, ok0 = false;
                int idx = 0;
                if (i < e) {
                    float4 p = d_cpts4[i];
                    idx = __float_as_int(p.w);
                    float p2 = fmaf(p.z, p.z, fmaf(p.y, p.y, p.x*p.x));
                    float dt = fmaf(qz, p.z, fmaf(qy, p.y, qx*p.x));
                    float d2 = fmaf(-2.f, dt, q2 + p2);
                    ok1 = d2 < 0.04f;
                    ok0 = d2 < 0.01f;
                }
                unsigned m1 = __ballot_sync(0xffffffffu, ok1);
                unsigned m0 = __ballot_sync(0xffffffffu, ok0);
                if (ok1) {
                    lmin1 = min(lmin1, idx);
                    int pos = cnt1 + __popc(m1 & low);
                    if (pos < CAP1) {
                        cand1[w][pos] = idx;
                        atomicAdd(&bc1[w][idx >> 9], 1);
                    }
                }
                if (ok0) {
                    lmin0 = min(lmin0, idx);
                    int pos = cnt0 + __popc(m0 & low);
                    if (pos < CAP0) {
                        cand0[w][pos] = idx;
                        atomicAdd(&bc0[w][idx >> 9], 1);
                    }
                }
                cnt1 += __popc(m1);
                cnt0 += __popc(m0);
            }
        }
    }
    cnt1 = min(cnt1, CAP1);
    cnt0 = min(cnt0, CAP0);
    #pragma unroll
    for (int d = 16; d; d >>= 1) {
        lmin1 = min(lmin1, __shfl_xor_sync(0xffffffffu, lmin1, d));
        lmin0 = min(lmin0, __shfl_xor_sync(0xffffffffu, lmin0, d));
    }
    __syncwarp();

    int m1n = select_k(cand1[w], cnt1, bc1[w], sel2[w], fin1[w], NS1, lane, low);
    __syncwarp();
    int m0n = select_k(cand0[w], cnt0, bc0[w], sel2[w], fin0[w], NS0, lane, low);
    __syncwarp();

    {   // scale 1 grouping
        int sidx = q * NS1 + lane;
        float g[19];
        if (m1n == 0) {
            #pragma unroll
            for (int c = 0; c < 19; c++) g[c] = 0.f;
        } else {
            int id = (lane < m1n) ? fin1[w][lane] : lmin1;
            float4 p = d_pts4[nbase + id];
            g[0] = p.x - qx; g[1] = p.y - qy; g[2] = p.z - qz;
            const float4* f = (const float4*)(feat + (size_t)(nbase + id) * CINF);
            float4 f0 = f[0], f1 = f[1], f2 = f[2], f3 = f[3];
            g[3]=f0.x; g[4]=f0.y; g[5]=f0.z; g[6]=f0.w;
            g[7]=f1.x; g[8]=f1.y; g[9]=f1.z; g[10]=f1.w;
            g[11]=f2.x; g[12]=f2.y; g[13]=f2.z; g[14]=f2.w;
            g[15]=f3.x; g[16]=f3.y; g[17]=f3.z; g[18]=f3.w;
        }
        #pragma unroll
        for (int c = 0; c < 19; c++) d_g1[c * NT1 + sidx] = g[c];
    }
    if (lane < NS0) {   // scale 0 grouping
        int sidx = q * NS0 + lane;
        float g[19];
        if (m0n == 0) {
            #pragma unroll
            for (int c = 0; c < 19; c++) g[c] = 0.f;
        } else {
            int id = (lane < m0n) ? fin0[w][lane] : lmin0;
            float4 p = d_pts4[nbase + id];
            g[0] = p.x - qx; g[1] = p.y - qy; g[2] = p.z - qz;
            const float4* f = (const float4*)(feat + (size_t)(nbase + id) * CINF);
            float4 f0 = f[0], f1 = f[1], f2 = f[2], f3 = f[3];
            g[3]=f0.x; g[4]=f0.y; g[5]=f0.z; g[6]=f0.w;
            g[7]=f1.x; g[8]=f1.y; g[9]=f1.z; g[10]=f1.w;
            g[11]=f2.x; g[12]=f2.y; g[13]=f2.z; g[14]=f2.w;
            g[15]=f3.x; g[16]=f3.y; g[17]=f3.z; g[18]=f3.w;
        }
        #pragma unroll
        for (int c = 0; c < 19; c++) d_g0[c * NT0 + sidx] = g[c];
    }
}

// ---------------- GEMV body (SPT=2, 256-thread blocks) ---------------------
template<int CIN, int CINP, int COUT, bool AFF>
__device__ __forceinline__ void gemv_body(
    int bid, const float* __restrict__ in, int ntot,
    const float* __restrict__ W,
    const float* __restrict__ gamma_, const float* __restrict__ beta_,
    float pN, int poff, float* __restrict__ out, int off,
    float* __restrict__ sW, float* __restrict__ sS, float* __restrict__ sB,
    float* __restrict__ shm, float* __restrict__ shq)
{
    for (int i = threadIdx.x; i < COUT * CINP; i += 256) {
        int o = i / CINP, c = i % CINP;
        sW[i] = (c < CIN) ? W[o * CIN + c] : 0.f;
    }
    for (int i = threadIdx.x; i < COUT; i += 256) { shm[i] = 0.f; shq[i] = 0.f; }
    if (AFF) {
        for (int i = threadIdx.x; i < CIN; i += 256) {
            double inv  = 1.0 / (double)pN;
            double mean = d_scr.sum[poff + i] * inv;
            double var  = d_scr.sqs[poff + i] * inv - mean * mean;
            double sc   = (double)gamma_[i] * rsqrt(var + 1e-5);
            sS[i] = (float)sc;
            sB[i] = (float)((double)beta_[i] - mean * sc);
        }
    }
    __syncthreads();

    int s    = (bid * 256 + threadIdx.x) * 2;
    int lane = threadIdx.x & 31;

    float2 x[CINP];
    #pragma unroll
    for (int c = 0; c < CINP; c++) {
        float2 v = make_float2(0.f, 0.f);
        if (c < CIN) {
            v = *(const float2*)&in[(size_t)c * ntot + s];
            if (AFF) {
                v.x = fmaxf(fmaf(v.x, sS[c], sB[c]), 0.f);
                v.y = fmaxf(fmaf(v.y, sS[c], sB[c]), 0.f);
            }
        }
        x[c] = v;
    }

    const float4* sW4 = (const float4*)sW;
    #pragma unroll
    for (int o = 0; o < COUT; o++) {
        float ax = 0.f, ay = 0.f;
        #pragma unroll
        for (int c4 = 0; c4 < CINP / 4; c4++) {
            float4 wv = sW4[o * (CINP / 4) + c4];
            ax = fmaf(x[c4*4+0].x, wv.x, ax); ay = fmaf(x[c4*4+0].y, wv.x, ay);
            ax = fmaf(x[c4*4+1].x, wv.y, ax); ay = fmaf(x[c4*4+1].y, wv.y, ay);
            ax = fmaf(x[c4*4+2].x, wv.z, ax); ay = fmaf(x[c4*4+2].y, wv.z, ay);
            ax = fmaf(x[c4*4+3].x, wv.w, ax); ay = fmaf(x[c4*4+3].y, wv.w, ay);
        }
        *(float2*)&out[(size_t)o * ntot + s] = make_float2(ax, ay);
        float sm = ax + ay;
        float sq = fmaf(ax, ax, ay * ay);
        #pragma unroll
        for (int d = 16; d; d >>= 1) {
            sm += __shfl_down_sync(0xffffffffu, sm, d);
            sq += __shfl_down_sync(0xffffffffu, sq, d);
        }
        if (lane == 0) { atomicAdd(&shm[o], sm); atomicAdd(&shq[o], sq); }
    }
    __syncthreads();
    if (threadIdx.x < COUT) {
        atomicAdd(&d_scr.sum[off + threadIdx.x], (double)shm[threadIdx.x]);
        atomicAdd(&d_scr.sqs[off + threadIdx.x], (double)shq[threadIdx.x]);
    }
}

// ---------------- kernel 4: fused layer-1 GEMVs (both scales, one launch) --
// blocks [0,256): scale1 (19->32, NT1). blocks [256,384): scale0 (19->16, NT0)
__global__ void __launch_bounds__(256) gemv_l1_kernel(
    const float* __restrict__ w10, const float* __restrict__ w00)
{
    __shared__ __align__(16) float sW[64 * 32];
    __shared__ float sS[32], sB[32], shm[64], shq[64];
    if (blockIdx.x < 256)
        gemv_body<19, 20, 32, false>(blockIdx.x, d_g1, NT1, w10,
                                     nullptr, nullptr, 0.f, 0,
                                     d_xa1, OFF_S1L1, sW, sS, sB, shm, shq);
    else
        gemv_body<19, 20, 16, false>(blockIdx.x - 256, d_g0, NT0, w00,
                                     nullptr, nullptr, 0.f, 0,
                                     d_xa0, OFF_S0L1, sW, sS, sB, shm, shq);
}

// ---------------- kernel 5: fused layer-2 GEMVs ----------------------------
__global__ void __launch_bounds__(256) gemv_l2_kernel(
    const float* __restrict__ w11, const float* __restrict__ g10,
    const float* __restrict__ b10,
    const float* __restrict__ w01, const float* __restrict__ g00,
    const float* __restrict__ b00)
{
    __shared__ __align__(16) float sW[64 * 32];
    __shared__ float sS[32], sB[32], shm[64], shq[64];
    if (blockIdx.x < 256)
        gemv_body<32, 32, 64, true>(blockIdx.x, d_xa1, NT1, w11, g10, b10,
                                    (float)NT1, OFF_S1L1,
                                    d_xb1, OFF_S1L2, sW, sS, sB, shm, shq);
    else
        gemv_body<16, 16, 32, true>(blockIdx.x - 256, d_xa0, NT0, w01, g00, b00,
                                    (float)NT0, OFF_S0L1,
                                    d_xb0, OFF_S0L2, sW, sS, sB, shm, shq);
}

// ---------------- pool body -------------------------------------------------
template<int NS, int COUT>
__device__ __forceinline__ void pool_body(
    int bid, const float* __restrict__ x, int ntot, int off, float pN,
    const float* __restrict__ gamma_, const float* __restrict__ beta_,
    int col_off, int out_off, float* __restrict__ out,
    float* __restrict__ psc, float* __restrict__ pbi)
{
    if (threadIdx.x < COUT) {
        int i = threadIdx.x;
        double inv  = 1.0 / (double)pN;
        double mean = d_scr.sum[off + i] * inv;
        double var  = d_scr.sqs[off + i] * inv - mean * mean;
        double sc   = (double)gamma_[i] * rsqrt(var + 1e-5);
        psc[i] = (float)sc;
        pbi[i] = (float)((double)beta_[i] - mean * sc);
    }
    __syncthreads();

    int warp = (bid * 256 + threadIdx.x) >> 5;
    int lane = threadIdx.x & 31;
    int q = warp * (32 / NS) + lane / NS;
    int j = lane % NS;
    if (q >= NQK) return;
    #pragma unroll 4
    for (int o = 0; o < COUT; o++) {
        float v = fmaf(x[(size_t)o * ntot + q * NS + j], psc[o], pbi[o]);
        #pragma unroll
        for (int d = NS / 2; d; d >>= 1)
            v = fmaxf(v, __shfl_xor_sync(0xffffffffu, v, d));
        if (j == 0) out[out_off + q * 96 + col_off + o] = fmaxf(v, 0.f);
    }
}

// ---------------- kernel 6: fused pools (both scales, one launch) ----------
// blocks [0,512): scale1. blocks [512,768): scale0.
__global__ void __launch_bounds__(256) pool_kernel(
    const float* __restrict__ g11, const float* __restrict__ b11,
    const float* __restrict__ g01, const float* __restrict__ b01,
    int out_off, float* __restrict__ out)
{
    __shared__ float psc[64], pbi[64];
    if (blockIdx.x < 512)
        pool_body<NS1, 64>(blockIdx.x, d_xb1, NT1, OFF_S1L2, (float)NT1,
                           g11, b11, 32, out_off, out, psc, pbi);
    else
        pool_body<NS0, 32>(blockIdx.x - 512, d_xb0, NT0, OFF_S0L2, (float)NT0,
                           g01, b01, 0, out_off, out, psc, pbi);
}

// ---------------- launch ----------------------------------------------------
extern "C" void kernel_launch(void* const* d_in, const int* in_sizes, int n_in,
                              void* d_out, int out_size)
{
    const float* xyz  = (const float*)d_in[0];
    const float* nxyz = (const float*)d_in[2];
    const float* feat = (const float*)d_in[4];
    const float* w00 = (const float*)d_in[5];
    const float* g00 = (const float*)d_in[6];
    const float* b00 = (const float*)d_in[7];
    const float* w01 = (const float*)d_in[8];
    const float* g01 = (const float*)d_in[9];
    const float* b01 = (const float*)d_in[10];
    const float* w10 = (const float*)d_in[11];
    const float* g10 = (const float*)d_in[12];
    const float* b10 = (const float*)d_in[13];
    const float* w11 = (const float*)d_in[14];
    const float* g11 = (const float*)d_in[15];
    const float* b11 = (const float*)d_in[16];
    float* out = (float*)d_out;

    void* scr;
    cudaGetSymbolAddress(&scr, d_scr);

    int out_off = out_size - NQK * 96;
    if (out_off < 0) out_off = 0;
    if (out_off > 0)
        cudaMemcpyAsync(out, nxyz, (size_t)out_off * sizeof(float),
                        cudaMemcpyDeviceToDevice);

    cudaMemsetAsync(scr, 0, sizeof(Scratch));                   // 1

    prep_count_kernel<<<(2 * N_PERK + 255) / 256, 256>>>(xyz);  // 2
    scan_kernel<<<1, 1024>>>();                                 // 3
    scatter_kernel<<<(2 * N_PERK + 255) / 256, 256>>>();        // 4
    bq_fused_kernel<<<NQK / 4, 128>>>(nxyz, feat);              // 5
    gemv_l1_kernel<<<384, 256>>>(w10, w00);                     // 6 <- ncu capture
    gemv_l2_kernel<<<384, 256>>>(w11, g10, b10, w01, g00, b00); // 7
    pool_kernel<<<768, 256>>>(g11, b11, g01, b01, out_off, out);// 8
}

// round 7
// speedup vs baseline: 1.7773x; 1.0088x over previous
#include <cuda_runtime.h>
#include <limits.h>

// Problem constants (fixed by setup_inputs)
#define N_PERK 16384
#define NQK    4096      // B * M_PER
#define CINF   16
#define NS0    16
#define NS1    32
#define NT0    65536     // NQK * NS0
#define NT1    131072    // NQK * NS1

// channel offsets into the 144-wide BN stat arrays
#define OFF_S0L1 0
#define OFF_S0L2 16
#define OFF_S1L1 48
#define OFF_S1L2 80

#define GRIDR  10
#define NCELLS 1000
#define CAP1   768
#define CAP0   192

// ---------------- scratch (device globals; no allocation allowed) ----------
struct Scratch {
    int    cellcnt[2016];
    int    cellofs[2016];
    double sum[144];
    double sqs[144];
};
__device__ Scratch d_scr;
__device__ int    d_cellstart[2048];
__device__ float4 d_pts4 [2 * N_PERK]; // original order: (x,y,z,|p|^2)
__device__ float4 d_cpts4[2 * N_PERK]; // cell-sorted:    (x,y,z,|p|^2)
__device__ int    d_cidx [2 * N_PERK]; // cell-sorted:    original index (0..16383)
__device__ float  d_g0 [19 * NT0];
__device__ float  d_g1 [19 * NT1];
__device__ float  d_xa0[16 * NT0];
__device__ float  d_xb0[32 * NT0];
__device__ float  d_xa1[32 * NT1];
__device__ float  d_xb1[64 * NT1];

// ---------------- kernel 0: pack points + count cells -----------------------
__global__ void prep_count_kernel(const float* __restrict__ xyz)
{
    int i = blockIdx.x * blockDim.x + threadIdx.x;
    if (i >= 2 * N_PERK) return;
    float x = xyz[i*3+0], y = xyz[i*3+1], z = xyz[i*3+2];
    d_pts4[i] = make_float4(x, y, z, fmaf(z, z, fmaf(y, y, x*x)));
    int cx = min(GRIDR-1, max(0, (int)(x * 10.f)));
    int cy = min(GRIDR-1, max(0, (int)(y * 10.f)));
    int cz = min(GRIDR-1, max(0, (int)(z * 10.f)));
    int cell = (i >> 14) * NCELLS + (cz * GRIDR + cy) * GRIDR + cx;
    atomicAdd(&d_scr.cellcnt[cell], 1);
}

// ---------------- kernel 1: fused scan + scatter ----------------------------
// Every block redundantly computes the exclusive prefix of the 2000 cell
// counts in shared memory (cheap), block 0 publishes it to d_cellstart for
// the ball-query kernel; all blocks then scatter their points.
__global__ void __launch_bounds__(256) scatter_kernel()
{
    __shared__ int sstart[2048];
    __shared__ int warpsum[8], warpbase[8];
    int t = threadIdx.x;
    int lane = t & 31, w = t >> 5;

    int v[8];
    int loc = 0;
    int base = t * 8;
    #pragma unroll
    for (int j = 0; j < 8; j++) {
        int k = base + j;
        int c = (k < 2 * NCELLS) ? d_scr.cellcnt[k] : 0;
        v[j] = loc;            // exclusive within thread
        loc += c;
    }
    int inc = loc;
    #pragma unroll
    for (int d = 1; d < 32; d <<= 1) {
        int x = __shfl_up_sync(0xffffffffu, inc, d);
        if (lane >= d) inc += x;
    }
    if (lane == 31) warpsum[w] = inc;
    __syncthreads();
    if (t == 0) {
        int s = 0;
        #pragma unroll
        for (int i = 0; i < 8; i++) { warpbase[i] = s; s += warpsum[i]; }
    }
    __syncthreads();
    int tbase = warpbase[w] + (inc - loc);
    #pragma unroll
    for (int j = 0; j < 8; j++)
        sstart[base + j] = tbase + v[j];
    __syncthreads();

    if (blockIdx.x == 0)
        for (int k = t; k <= 2 * NCELLS; k += 256)
            d_cellstart[k] = (k < 2048) ? sstart[k] : 0;

    int i = blockIdx.x * 256 + t;
    if (i < 2 * N_PERK) {
        float4 p = d_pts4[i];
        int cx = min(GRIDR-1, max(0, (int)(p.x * 10.f)));
        int cy = min(GRIDR-1, max(0, (int)(p.y * 10.f)));
        int cz = min(GRIDR-1, max(0, (int)(p.z * 10.f)));
        int cell = (i >> 14) * NCELLS + (cz * GRIDR + cy) * GRIDR + cx;
        int pos = sstart[cell] + atomicAdd(&d_scr.cellofs[cell], 1);
        d_cpts4[pos] = p;                      // keeps |p|^2 in w
        d_cidx[pos]  = i & (N_PERK - 1);
    }
}

// ---------------- select k smallest indices from cand[cnt] -----------------
__device__ __forceinline__ int select_k(const int* __restrict__ cand, int cnt,
                                        const int* __restrict__ bc,
                                        int* __restrict__ sel2,
                                        int* __restrict__ fin,
                                        int k, int lane, unsigned low)
{
    if (cnt <= k) {
        for (int i = lane; i < cnt; i += 32) fin[i] = cand[i];
        return cnt;
    }
    int p = bc[lane];
    #pragma unroll
    for (int d = 1; d < 32; d <<= 1) {
        int t = __shfl_up_sync(0xffffffffu, p, d);
        if (lane >= d) p += t;
    }
    unsigned mk = __ballot_sync(0xffffffffu, p >= k);
    int bstar = __ffs(mk) - 1;
    int base  = (bstar > 0) ? __shfl_sync(0xffffffffu, p, bstar - 1) : 0;
    int need  = k - base;
    int B0 = bstar << 9, B1 = (bstar + 1) << 9;

    int n_auto = 0, n_mid = 0;
    for (int i0 = 0; i0 < cnt; i0 += 32) {
        int i = i0 + lane;
        int v = (i < cnt) ? cand[i] : INT_MAX;
        bool a = (v < B0);
        bool m = (v >= B0) && (v < B1);
        unsigned ma = __ballot_sync(0xffffffffu, a);
        unsigned mm = __ballot_sync(0xffffffffu, m);
        if (a) fin[n_auto + __popc(ma & low)] = v;
        else if (m) {
            int pos = n_mid + __popc(mm & low);
            if (pos < 64) sel2[pos] = v;
        }
        n_auto += __popc(ma);
        n_mid  += __popc(mm);
    }
    if (n_mid > 64) n_mid = 64;
    __syncwarp();

    int last = -1;
    for (int j = 0; j < need; j++) {
        int v = INT_MAX;
        for (int i = lane; i < n_mid; i += 32) {
            int x = sel2[i];
            if (x > last && x < v) v = x;
        }
        #pragma unroll
        for (int d = 16; d; d >>= 1)
            v = min(v, __shfl_xor_sync(0xffffffffu, v, d));
        fin[base + j] = v;
        last = v;
    }
    return k;
}

// ---------------- kernel 2: block-per-query dual-scale ball query ----------
// 4 warps cooperatively scan the (z,y) rows of the 5x5x5 cell neighborhood
// with exact per-row pruning; hits append to shared candidate arrays via
// warp-aggregated shared atomics. Warps 0/1 then select the NS1/NS0 smallest
// original indices concurrently; warps 0/1 emit the grouped features.
__global__ void __launch_bounds__(128) bq_block_kernel(
    const float* __restrict__ nxyz, const float* __restrict__ feat)
{
    __shared__ int cand1[CAP1], cand0[CAP0];
    __shared__ int bc1[32], bc0[32];
    __shared__ int sel2a[64], sel2b[64];
    __shared__ int fin1[NS1], fin0[NS0];
    __shared__ int scnt1, scnt0, slmin1, slmin0, m1n_s, m0n_s;

    int tid  = threadIdx.x;
    int wid  = tid >> 5;
    int lane = tid & 31;
    unsigned low = (1u << lane) - 1u;

    int q = blockIdx.x;
    int b = q >> 11;
    int nbase = b << 14;

    if (tid < 32) { bc1[tid] = 0; bc0[tid] = 0; }
    if (tid == 0) {
        scnt1 = 0; scnt0 = 0;
        slmin1 = INT_MAX; slmin0 = INT_MAX;
    }
    __syncthreads();

    float qx = nxyz[q*3+0], qy = nxyz[q*3+1], qz = nxyz[q*3+2];
    float q2 = fmaf(qz, qz, fmaf(qy, qy, qx*qx));

    int cy = min(GRIDR-1, max(0, (int)(qy * 10.f)));
    int cz = min(GRIDR-1, max(0, (int)(qz * 10.f)));
    int zlo = max(0, cz-2), zhi = min(GRIDR-1, cz+2);
    int ylo = max(0, cy-2), yhi = min(GRIDR-1, cy+2);
    int nz = zhi - zlo + 1, ny = yhi - ylo + 1;

    const float RP2 = 0.04f + 1e-4f;
    int lmin1 = INT_MAX, lmin0 = INT_MAX;

    for (int ri = wid; ri < nz * ny; ri += 4) {
        int zz = zlo + ri / ny;
        int yy = ylo + ri % ny;
        float dz = fmaxf(0.f, fmaxf(zz * 0.1f - qz, qz - (zz+1) * 0.1f));
        float dy = fmaxf(0.f, fmaxf(yy * 0.1f - qy, qy - (yy+1) * 0.1f));
        float r2 = fmaf(dy, dy, dz * dz);
        if (r2 >= RP2) continue;
        float dxm = sqrtf(RP2 - r2);
        int xlo = max(0, (int)floorf((qx - dxm) * 10.f));
        int xhi = min(GRIDR-1, (int)floorf((qx + dxm) * 10.f));
        if (xlo > xhi) continue;
        int row = b * NCELLS + (zz * GRIDR + yy) * GRIDR;
        int s = d_cellstart[row + xlo];
        int e = d_cellstart[row + xhi + 1];
        for (int i0 = s; i0 < e; i0 += 32) {
            int i = i0 + lane;
            bool ok1 = false, ok0 = false;
            int idx = 0;
            if (i < e) {
                float4 p = d_cpts4[i];
                idx = d_cidx[i];
                float dt = fmaf(qz, p.z, fmaf(qy, p.y, qx*p.x));
                float d2 = fmaf(-2.f, dt, q2 + p.w);   // matches reference rounding
                ok1 = d2 < 0.04f;
                ok0 = d2 < 0.01f;
            }
            unsigned m1 = __ballot_sync(0xffffffffu, ok1);
            unsigned m0 = __ballot_sync(0xffffffffu, ok0);
            if (m1) {
                int bpos = 0;
                if (lane == 0) bpos = atomicAdd(&scnt1, __popc(m1));
                bpos = __shfl_sync(0xffffffffu, bpos, 0);
                if (ok1) {
                    lmin1 = min(lmin1, idx);
                    int pos = bpos + __popc(m1 & low);
                    if (pos < CAP1) {
                        cand1[pos] = idx;
                        atomicAdd(&bc1[idx >> 9], 1);
                    }
                }
            }
            if (m0) {
                int bpos = 0;
                if (lane == 0) bpos = atomicAdd(&scnt0, __popc(m0));
                bpos = __shfl_sync(0xffffffffu, bpos, 0);
                if (ok0) {
                    lmin0 = min(lmin0, idx);
                    int pos = bpos + __popc(m0 & low);
                    if (pos < CAP0) {
                        cand0[pos] = idx;
                        atomicAdd(&bc0[idx >> 9], 1);
                    }
                }
            }
        }
    }
    #pragma unroll
    for (int d = 16; d; d >>= 1) {
        lmin1 = min(lmin1, __shfl_xor_sync(0xffffffffu, lmin1, d));
        lmin0 = min(lmin0, __shfl_xor_sync(0xffffffffu, lmin0, d));
    }
    if (lane == 0) {
        atomicMin(&slmin1, lmin1);
        atomicMin(&slmin0, lmin0);
    }
    __syncthreads();

    if (wid == 0) {
        int n = select_k(cand1, min(scnt1, CAP1), bc1, sel2a, fin1, NS1, lane, low);
        if (lane == 0) m1n_s = n;
    } else if (wid == 1) {
        int n = select_k(cand0, min(scnt0, CAP0), bc0, sel2b, fin0, NS0, lane, low);
        if (lane == 0) m0n_s = n;
    }
    __syncthreads();

    if (wid == 0) {   // scale-1 grouping (32 lanes)
        int m1n = m1n_s;
        int sidx = q * NS1 + lane;
        float g[19];
        if (m1n == 0) {
            #pragma unroll
            for (int c = 0; c < 19; c++) g[c] = 0.f;
        } else {
            int id = (lane < m1n) ? fin1[lane] : slmin1;
            float4 p = d_pts4[nbase + id];
            g[0] = p.x - qx; g[1] = p.y - qy; g[2] = p.z - qz;
            const float4* f = (const float4*)(feat + (size_t)(nbase + id) * CINF);
            float4 f0 = f[0], f1 = f[1], f2 = f[2], f3 = f[3];
            g[3]=f0.x; g[4]=f0.y; g[5]=f0.z; g[6]=f0.w;
            g[7]=f1.x; g[8]=f1.y; g[9]=f1.z; g[10]=f1.w;
            g[11]=f2.x; g[12]=f2.y; g[13]=f2.z; g[14]=f2.w;
            g[15]=f3.x; g[16]=f3.y; g[17]=f3.z; g[18]=f3.w;
        }
        #pragma unroll
        for (int c = 0; c < 19; c++) d_g1[c * NT1 + sidx] = g[c];
    } else if (wid == 1 && lane < NS0) {   // scale-0 grouping (16 lanes)
        int m0n = m0n_s;
        int sidx = q * NS0 + lane;
        float g[19];
        if (m0n == 0) {
            #pragma unroll
            for (int c = 0; c < 19; c++) g[c] = 0.f;
        } else {
            int id = (lane < m0n) ? fin0[lane] : slmin0;
            float4 p = d_pts4[nbase + id];
            g[0] = p.x - qx; g[1] = p.y - qy; g[2] = p.z - qz;
            const float4* f = (const float4*)(feat + (size_t)(nbase + id) * CINF);
            float4 f0 = f[0], f1 = f[1], f2 = f[2], f3 = f[3];
            g[3]=f0.x; g[4]=f0.y; g[5]=f0.z; g[6]=f0.w;
            g[7]=f1.x; g[8]=f1.y; g[9]=f1.z; g[10]=f1.w;
            g[11]=f2.x; g[12]=f2.y; g[13]=f2.z; g[14]=f2.w;
            g[15]=f3.x; g[16]=f3.y; g[17]=f3.z; g[18]=f3.w;
        }
        #pragma unroll
        for (int c = 0; c < 19; c++) d_g0[c * NT0 + sidx] = g[c];
    }
}

// ---------------- GEMV body (SPT=2, 256-thread blocks) ---------------------
template<int CIN, int CINP, int COUT, bool AFF>
__device__ __forceinline__ void gemv_body(
    int bid, const float* __restrict__ in, int ntot,
    const float* __restrict__ W,
    const float* __restrict__ gamma_, const float* __restrict__ beta_,
    float pN, int poff, float* __restrict__ out, int off,
    float* __restrict__ sW, float* __restrict__ sS, float* __restrict__ sB,
    float* __restrict__ shm, float* __restrict__ shq)
{
    for (int i = threadIdx.x; i < COUT * CINP; i += 256) {
        int o = i / CINP, c = i % CINP;
        sW[i] = (c < CIN) ? W[o * CIN + c] : 0.f;
    }
    for (int i = threadIdx.x; i < COUT; i += 256) { shm[i] = 0.f; shq[i] = 0.f; }
    if (AFF) {
        for (int i = threadIdx.x; i < CIN; i += 256) {
            double inv  = 1.0 / (double)pN;
            double mean = d_scr.sum[poff + i] * inv;
            double var  = d_scr.sqs[poff + i] * inv - mean * mean;
            double sc   = (double)gamma_[i] * rsqrt(var + 1e-5);
            sS[i] = (float)sc;
            sB[i] = (float)((double)beta_[i] - mean * sc);
        }
    }
    __syncthreads();

    int s    = (bid * 256 + threadIdx.x) * 2;
    int lane = threadIdx.x & 31;

    float2 x[CINP];
    #pragma unroll
    for (int c = 0; c < CINP; c++) {
        float2 v = make_float2(0.f, 0.f);
        if (c < CIN) {
            v = *(const float2*)&in[(size_t)c * ntot + s];
            if (AFF) {
                v.x = fmaxf(fmaf(v.x, sS[c], sB[c]), 0.f);
                v.y = fmaxf(fmaf(v.y, sS[c], sB[c]), 0.f);
            }
        }
        x[c] = v;
    }

    const float4* sW4 = (const float4*)sW;
    #pragma unroll
    for (int o = 0; o < COUT; o++) {
        float ax = 0.f, ay = 0.f;
        #pragma unroll
        for (int c4 = 0; c4 < CINP / 4; c4++) {
            float4 wv = sW4[o * (CINP / 4) + c4];
            ax = fmaf(x[c4*4+0].x, wv.x, ax); ay = fmaf(x[c4*4+0].y, wv.x, ay);
            ax = fmaf(x[c4*4+1].x, wv.y, ax); ay = fmaf(x[c4*4+1].y, wv.y, ay);
            ax = fmaf(x[c4*4+2].x, wv.z, ax); ay = fmaf(x[c4*4+2].y, wv.z, ay);
            ax = fmaf(x[c4*4+3].x, wv.w, ax); ay = fmaf(x[c4*4+3].y, wv.w, ay);
        }
        *(float2*)&out[(size_t)o * ntot + s] = make_float2(ax, ay);
        float sm = ax + ay;
        float sq = fmaf(ax, ax, ay * ay);
        #pragma unroll
        for (int d = 16; d; d >>= 1) {
            sm += __shfl_down_sync(0xffffffffu, sm, d);
            sq += __shfl_down_sync(0xffffffffu, sq, d);
        }
        if (lane == 0) { atomicAdd(&shm[o], sm); atomicAdd(&shq[o], sq); }
    }
    __syncthreads();
    if (threadIdx.x < COUT) {
        atomicAdd(&d_scr.sum[off + threadIdx.x], (double)shm[threadIdx.x]);
        atomicAdd(&d_scr.sqs[off + threadIdx.x], (double)shq[threadIdx.x]);
    }
}

// ---------------- kernel 3: fused layer-1 GEMVs ----------------------------
__global__ void __launch_bounds__(256) gemv_l1_kernel(
    const float* __restrict__ w10, const float* __restrict__ w00)
{
    __shared__ __align__(16) float sW[64 * 32];
    __shared__ float sS[32], sB[32], shm[64], shq[64];
    if (blockIdx.x < 256)
        gemv_body<19, 20, 32, false>(blockIdx.x, d_g1, NT1, w10,
                                     nullptr, nullptr, 0.f, 0,
                                     d_xa1, OFF_S1L1, sW, sS, sB, shm, shq);
    else
        gemv_body<19, 20, 16, false>(blockIdx.x - 256, d_g0, NT0, w00,
                                     nullptr, nullptr, 0.f, 0,
                                     d_xa0, OFF_S0L1, sW, sS, sB, shm, shq);
}

// ---------------- kernel 4: fused layer-2 GEMVs ----------------------------
__global__ void __launch_bounds__(256) gemv_l2_kernel(
    const float* __restrict__ w11, const float* __restrict__ g10,
    const float* __restrict__ b10,
    const float* __restrict__ w01, const float* __restrict__ g00,
    const float* __restrict__ b00)
{
    __shared__ __align__(16) float sW[64 * 32];
    __shared__ float sS[32], sB[32], shm[64], shq[64];
    if (blockIdx.x < 256)
        gemv_body<32, 32, 64, true>(blockIdx.x, d_xa1, NT1, w11, g10, b10,
                                    (float)NT1, OFF_S1L1,
                                    d_xb1, OFF_S1L2, sW, sS, sB, shm, shq);
    else
        gemv_body<16, 16, 32, true>(blockIdx.x - 256, d_xa0, NT0, w01, g00, b00,
                                    (float)NT0, OFF_S0L1,
                                    d_xb0, OFF_S0L2, sW, sS, sB, shm, shq);
}

// ---------------- pool body -------------------------------------------------
template<int NS, int COUT>
__device__ __forceinline__ void pool_body(
    int bid, const float* __restrict__ x, int ntot, int off, float pN,
    const float* __restrict__ gamma_, const float* __restrict__ beta_,
    int col_off, int out_off, float* __restrict__ out,
    float* __restrict__ psc, float* __restrict__ pbi)
{
    if (threadIdx.x < COUT) {
        int i = threadIdx.x;
        double inv  = 1.0 / (double)pN;
        double mean = d_scr.sum[off + i] * inv;
        double var  = d_scr.sqs[off + i] * inv - mean * mean;
        double sc   = (double)gamma_[i] * rsqrt(var + 1e-5);
        psc[i] = (float)sc;
        pbi[i] = (float)((double)beta_[i] - mean * sc);
    }
    __syncthreads();

    int warp = (bid * 256 + threadIdx.x) >> 5;
    int lane = threadIdx.x & 31;
    int q = warp * (32 / NS) + lane / NS;
    int j = lane % NS;
    if (q >= NQK) return;
    #pragma unroll 4
    for (int o = 0; o < COUT; o++) {
        float v = fmaf(x[(size_t)o * ntot + q * NS + j], psc[o], pbi[o]);
        #pragma unroll
        for (int d = NS / 2; d; d >>= 1)
            v = fmaxf(v, __shfl_xor_sync(0xffffffffu, v, d));
        if (j == 0) out[out_off + q * 96 + col_off + o] = fmaxf(v, 0.f);
    }
}

// ---------------- kernel 5: fused pools ------------------------------------
__global__ void __launch_bounds__(256) pool_kernel(
    const float* __restrict__ g11, const float* __restrict__ b11,
    const float* __restrict__ g01, const float* __restrict__ b01,
    int out_off, float* __restrict__ out)
{
    __shared__ float psc[64], pbi[64];
    if (blockIdx.x < 512)
        pool_body<NS1, 64>(blockIdx.x, d_xb1, NT1, OFF_S1L2, (float)NT1,
                           g11, b11, 32, out_off, out, psc, pbi);
    else
        pool_body<NS0, 32>(blockIdx.x - 512, d_xb0, NT0, OFF_S0L2, (float)NT0,
                           g01, b01, 0, out_off, out, psc, pbi);
}

// ---------------- launch ----------------------------------------------------
extern "C" void kernel_launch(void* const* d_in, const int* in_sizes, int n_in,
                              void* d_out, int out_size)
{
    const float* xyz  = (const float*)d_in[0];
    const float* nxyz = (const float*)d_in[2];
    const float* feat = (const float*)d_in[4];
    const float* w00 = (const float*)d_in[5];
    const float* g00 = (const float*)d_in[6];
    const float* b00 = (const float*)d_in[7];
    const float* w01 = (const float*)d_in[8];
    const float* g01 = (const float*)d_in[9];
    const float* b01 = (const float*)d_in[10];
    const float* w10 = (const float*)d_in[11];
    const float* g10 = (const float*)d_in[12];
    const float* b10 = (const float*)d_in[13];
    const float* w11 = (const float*)d_in[14];
    const float* g11 = (const float*)d_in[15];
    const float* b11 = (const float*)d_in[16];
    float* out = (float*)d_out;

    void* scr;
    cudaGetSymbolAddress(&scr, d_scr);

    int out_off = out_size - NQK * 96;
    if (out_off < 0) out_off = 0;
    if (out_off > 0)
        cudaMemcpyAsync(out, nxyz, (size_t)out_off * sizeof(float),
                        cudaMemcpyDeviceToDevice);

    cudaMemsetAsync(scr, 0, sizeof(Scratch));

    prep_count_kernel<<<(2 * N_PERK + 255) / 256, 256>>>(xyz);
    scatter_kernel<<<(2 * N_PERK + 255) / 256, 256>>>();
    bq_block_kernel<<<NQK, 128>>>(nxyz, feat);
    gemv_l1_kernel<<<384, 256>>>(w10, w00);
    gemv_l2_kernel<<<384, 256>>>(w11, g10, b10, w01, g00, b00);
    pool_kernel<<<768, 256>>>(g11, b11, g01, b01, out_off, out);
}